// round 16
// baseline (speedup 1.0000x reference)
#include <cuda_runtime.h>
#include <cuda_fp16.h>
#include <math.h>
#include <stdint.h>

// Problem constants
#define B_  4
#define N_  4096
#define U_  512
#define M1  (B_ * N_)
#define QKVLD 1536

// GEMM tiling: CTA 128x128, 8 warps 64x32, BK=64, 3-stage cp.async pipeline
#define BM 128
#define BN 128
#define SKB 144          // smem row stride bytes (128 data + 16 pad)
#define NSTAGE 3

static constexpr int ATILE  = BM * SKB;            // 18432 B
static constexpr int STAGEB = 2 * ATILE;
static constexpr int SM_TOTAL = NSTAGE * STAGEB;   // 110592 B

// ---------------- scratch (device globals; no allocation allowed) ----------
__device__ __align__(16) __half g_xh  [(size_t)M1 * U_];
__device__ __align__(16) __half g_QKV [(size_t)M1 * QKVLD];    // Q|K|V per row
__device__ __align__(16) __half g_VT  [(size_t)M1 * U_];       // per batch [U, N]
__device__ __align__(16) __half g_S   [(size_t)B_ * N_ * N_];  // 128 MB scores/probs
__device__ __align__(16) __half g_C   [(size_t)M1 * U_];       // ctx
__device__ __align__(16) __half g_WQKVT[(size_t)3 * U_ * U_];  // [1536,512]
__device__ __align__(16) __half g_WPT [(size_t)U_ * U_];
__device__ __align__(16) float  g_bqkv[QKVLD];

// ---------------- PTX helpers ----------------------------------------------
__device__ __forceinline__ uint32_t smem_u32(const void* p) {
    uint32_t a;
    asm("{ .reg .u64 t; cvta.to.shared.u64 t, %1; cvt.u32.u64 %0, t; }" : "=r"(a) : "l"(p));
    return a;
}
#define CP_ASYNC16(dst, src) \
    asm volatile("cp.async.cg.shared.global [%0], [%1], 16;\n" :: "r"(dst), "l"(src))
#define CP_COMMIT() asm volatile("cp.async.commit_group;\n" ::: "memory")
#define CP_WAIT(n)  asm volatile("cp.async.wait_group %0;\n" :: "n"(n) : "memory")

__device__ __forceinline__ void ldsm_x4(uint32_t& r0, uint32_t& r1, uint32_t& r2,
                                        uint32_t& r3, uint32_t addr) {
    asm volatile("ldmatrix.sync.aligned.m8n8.x4.shared.b16 {%0,%1,%2,%3}, [%4];"
                 : "=r"(r0), "=r"(r1), "=r"(r2), "=r"(r3) : "r"(addr));
}
// f16 x f16 -> f16 accumulate; c = two packed f16x2 regs
__device__ __forceinline__ void mma_f16(uint32_t c[2],
                                        uint32_t a0, uint32_t a1, uint32_t a2, uint32_t a3,
                                        uint32_t b0, uint32_t b1) {
    asm volatile(
        "mma.sync.aligned.m16n8k16.row.col.f16.f16.f16.f16 "
        "{%0,%1}, {%2,%3,%4,%5}, {%6,%7}, {%0,%1};\n"
        : "+r"(c[0]), "+r"(c[1])
        : "r"(a0), "r"(a1), "r"(a2), "r"(a3), "r"(b0), "r"(b1));
}

// ---------------------------------------------------------------------------
// fp16 NT GEMM (f16 accum):  C[z] = scale * A[z] @ B[z]^T (+bias) (+residual)
// A: [M,K] lda-strided __half. B: [N,K] ldb-strided __half.
// 256 threads, 8 warps 64x32. 3-stage cp.async pipeline, 1 barrier/ktile.
// OF16: output __half, else fp32 (+residual).
// ---------------------------------------------------------------------------
template <bool OF16>
__global__ __launch_bounds__(256, 2)
void gemm_f16(const __half* __restrict__ A,
              const __half* __restrict__ Bm,
              const float* __restrict__ bias,
              const float* __restrict__ residual,
              void* __restrict__ Cout,
              int N, int K, int lda, int ldb, int ldc,
              long long sA, long long sB, long long sC,
              float scale)
{
    extern __shared__ char smem[];
    const uint32_t sbase = smem_u32(smem);
    const int tid  = threadIdx.x;
    const int wid  = tid >> 5;
    const int lane = tid & 31;

    const int z = blockIdx.z;
    A  += (long long)z * sA;
    Bm += (long long)z * sB;

    const int rowBase = blockIdx.y * BM;
    const int colBase = blockIdx.x * BN;
    const int warpM = (wid & 1) * 64;
    const int warpN = (wid >> 1) * 32;

    const __half* Aptr = A + (long long)rowBase * lda;
    const __half* Bptr = Bm + (long long)colBase * ldb;

    uint32_t acc[4][4][2];
    #pragma unroll
    for (int mi = 0; mi < 4; mi++)
        #pragma unroll
        for (int ni = 0; ni < 4; ni++) {
            acc[mi][ni][0] = 0u; acc[mi][ni][1] = 0u;
        }

    const int lr = tid >> 3;
    const int lc = tid & 7;
    auto load_tile = [&](int s, int k0) {
        const uint32_t abase = sbase + s * STAGEB;
        const uint32_t bbase = abase + ATILE;
        #pragma unroll
        for (int i = 0; i < 4; i++) {
            const int r = lr + i * 32;
            CP_ASYNC16(abase + r * SKB + lc * 16,
                       Aptr + (long long)r * lda + k0 + lc * 8);
        }
        #pragma unroll
        for (int i = 0; i < 4; i++) {
            const int r = lr + i * 32;
            CP_ASYNC16(bbase + r * SKB + lc * 16,
                       Bptr + (long long)r * ldb + k0 + lc * 8);
        }
        CP_COMMIT();
    };

    const int lm = lane & 7;
    const int lt = lane >> 3;
    const int aRowOff = lm + (lt & 1) * 8;
    const int aKOff   = (lt >> 1) * 8;
    const int bRowOff = lm + (lt >> 1) * 8;
    const int bKOff   = (lt & 1) * 8;

    const int T = K / 64;
    load_tile(0, 0);
    if (T > 1) load_tile(1, 64);

    int sIdx = 0;
    for (int t = 0; t < T; t++) {
        if (t + 1 < T) { CP_WAIT(1); } else { CP_WAIT(0); }
        __syncthreads();
        if (t + 2 < T) {
            int s2 = sIdx + 2; if (s2 >= NSTAGE) s2 -= NSTAGE;
            load_tile(s2, (t + 2) * 64);
        }

        const uint32_t Asb = sbase + sIdx * STAGEB;
        const uint32_t Bsb = Asb + ATILE;

        #pragma unroll
        for (int kk = 0; kk < 4; kk++) {
            uint32_t a[4][4], b[4][2];
            #pragma unroll
            for (int mi = 0; mi < 4; mi++) {
                uint32_t addr = Asb + (warpM + mi * 16 + aRowOff) * SKB
                              + (kk * 16 + aKOff) * 2;
                ldsm_x4(a[mi][0], a[mi][1], a[mi][2], a[mi][3], addr);
            }
            #pragma unroll
            for (int p = 0; p < 2; p++) {
                uint32_t addr = Bsb + (warpN + p * 16 + bRowOff) * SKB
                              + (kk * 16 + bKOff) * 2;
                uint32_t r0, r1, r2, r3;
                ldsm_x4(r0, r1, r2, r3, addr);
                b[2*p][0] = r0;   b[2*p][1] = r1;
                b[2*p+1][0] = r2; b[2*p+1][1] = r3;
            }
            #pragma unroll
            for (int mi = 0; mi < 4; mi++)
                #pragma unroll
                for (int ni = 0; ni < 4; ni++)
                    mma_f16(acc[mi][ni], a[mi][0], a[mi][1], a[mi][2], a[mi][3],
                            b[ni][0], b[ni][1]);
        }
        sIdx++; if (sIdx >= NSTAGE) sIdx = 0;
    }

    // ---- epilogue ----
    #pragma unroll
    for (int mi = 0; mi < 4; mi++) {
        #pragma unroll
        for (int ni = 0; ni < 4; ni++) {
            const int row0 = rowBase + warpM + mi * 16 + (lane >> 2);
            const int col  = colBase + warpN + ni * 8 + (lane & 3) * 2;
            float2 v01 = __half22float2(*reinterpret_cast<__half2*>(&acc[mi][ni][0]));
            float2 v23 = __half22float2(*reinterpret_cast<__half2*>(&acc[mi][ni][1]));
            float v[4] = { v01.x * scale, v01.y * scale, v23.x * scale, v23.y * scale };
            if (bias) {
                const float b0 = bias[col], b1 = bias[col + 1];
                v[0] += b0; v[1] += b1; v[2] += b0; v[3] += b1;
            }
            if (!OF16) {
                float* C = (float*)Cout + (long long)z * sC;
                if (residual) {
                    const float* R = residual + (long long)z * sC;
                    float2 r0 = *reinterpret_cast<const float2*>(&R[(long long)row0 * ldc + col]);
                    float2 r1 = *reinterpret_cast<const float2*>(&R[(long long)(row0 + 8) * ldc + col]);
                    v[0] += r0.x; v[1] += r0.y; v[2] += r1.x; v[3] += r1.y;
                }
                *reinterpret_cast<float2*>(&C[(long long)row0 * ldc + col])       = make_float2(v[0], v[1]);
                *reinterpret_cast<float2*>(&C[(long long)(row0 + 8) * ldc + col]) = make_float2(v[2], v[3]);
            } else {
                __half* C = (__half*)Cout + (long long)z * sC;
                __half2 p0 = __floats2half2_rn(v[0], v[1]);
                __half2 p1 = __floats2half2_rn(v[2], v[3]);
                *reinterpret_cast<uint32_t*>(&C[(long long)row0 * ldc + col])       = *(uint32_t*)&p0;
                *reinterpret_cast<uint32_t*>(&C[(long long)(row0 + 8) * ldc + col]) = *(uint32_t*)&p1;
            }
        }
    }
}

// ---------------------------------------------------------------------------
// setup: fp32 -> fp16 x, pack biases, weight transposes
// ---------------------------------------------------------------------------
__global__ __launch_bounds__(256)
void conv_f16(const float* __restrict__ in, __half* __restrict__ out, long long n)
{
    long long i = ((long long)blockIdx.x * blockDim.x + threadIdx.x) * 4;
    if (i >= n) return;
    float4 f = *reinterpret_cast<const float4*>(in + i);
    __half2 p0 = __floats2half2_rn(f.x, f.y);
    __half2 p1 = __floats2half2_rn(f.z, f.w);
    uint2 o; o.x = *(uint32_t*)&p0; o.y = *(uint32_t*)&p1;
    *reinterpret_cast<uint2*>(out + i) = o;
}

__global__ __launch_bounds__(256)
void pack_bias(const float* __restrict__ bq, const float* __restrict__ bk,
               const float* __restrict__ bv, float* __restrict__ bqkv)
{
    int i = blockIdx.x * blockDim.x + threadIdx.x;
    if (i < U_)              bqkv[i] = bq[i];
    else if (i < 2 * U_)     bqkv[i] = bk[i - U_];
    else if (i < 3 * U_)     bqkv[i] = bv[i - 2 * U_];
}

// all-weights transpose fp32->fp16: z in {0:Wq,1:Wk,2:Wv,3:Wp}
__global__ __launch_bounds__(256)
void wtrans_all(const float* __restrict__ Wq, const float* __restrict__ Wk,
                const float* __restrict__ Wv, const float* __restrict__ Wp,
                __half* __restrict__ Wqkvt, __half* __restrict__ Wpt)
{
    __shared__ float tile[32][33];
    const int z = blockIdx.z;
    const float* in = (z == 0) ? Wq : (z == 1) ? Wk : (z == 2) ? Wv : Wp;
    __half* out = (z < 3) ? (Wqkvt + (size_t)z * U_ * U_) : Wpt;
    const int c0 = blockIdx.x * 32, r0 = blockIdx.y * 32;
    const int x = threadIdx.x, y = threadIdx.y;
    #pragma unroll
    for (int i = 0; i < 32; i += 8)
        tile[y + i][x] = in[(long long)(r0 + y + i) * U_ + c0 + x];
    __syncthreads();
    #pragma unroll
    for (int i = 0; i < 32; i += 8)
        out[(long long)(c0 + y + i) * U_ + r0 + x] = __float2half(tile[x][y + i]);
}

// V (inside QKV, row stride 1536, col offset 1024) -> VT [U, N] per batch
__global__ __launch_bounds__(256)
void vtrans(const __half* __restrict__ qkv, __half* __restrict__ vt)
{
    __shared__ __half tile[32][34];
    const int z = blockIdx.z;
    const __half* in = qkv + (long long)z * N_ * QKVLD + 2 * U_;
    __half* out = vt + (long long)z * N_ * U_;
    const int c0 = blockIdx.x * 32, r0 = blockIdx.y * 32;
    const int x = threadIdx.x, y = threadIdx.y;
    #pragma unroll
    for (int i = 0; i < 32; i += 8)
        tile[y + i][x] = in[(long long)(r0 + y + i) * QKVLD + c0 + x];
    __syncthreads();
    #pragma unroll
    for (int i = 0; i < 32; i += 8)
        out[(long long)(c0 + y + i) * N_ + r0 + x] = tile[x][y + i];
}

// ---------------------------------------------------------------------------
// row softmax on fp16 [rows x 4096], in place; warp-shuffle reductions
// ---------------------------------------------------------------------------
__global__ __launch_bounds__(256)
void softmax_f16(__half* __restrict__ S)
{
    const long long row = blockIdx.x;
    uint4* p = reinterpret_cast<uint4*>(S + row * (long long)N_);
    const int tid = threadIdx.x;
    const int lane = tid & 31, wp = tid >> 5;
    __shared__ float red[8];

    uint4 u[2];
    u[0] = p[tid * 2];
    u[1] = p[tid * 2 + 1];

    float f[16];
    {
        const __half2* h = reinterpret_cast<const __half2*>(u);
        #pragma unroll
        for (int i = 0; i < 8; i++) {
            float2 t = __half22float2(h[i]);
            f[i * 2] = t.x; f[i * 2 + 1] = t.y;
        }
    }

    float m = f[0];
    #pragma unroll
    for (int i = 1; i < 16; i++) m = fmaxf(m, f[i]);
    #pragma unroll
    for (int o = 16; o > 0; o >>= 1)
        m = fmaxf(m, __shfl_xor_sync(0xFFFFFFFF, m, o));
    if (lane == 0) red[wp] = m;
    __syncthreads();
    {
        float t = red[lane & 7];
        #pragma unroll
        for (int o = 4; o > 0; o >>= 1)
            t = fmaxf(t, __shfl_xor_sync(0xFFFFFFFF, t, o));
        m = t;
    }

    float sum = 0.0f;
    #pragma unroll
    for (int i = 0; i < 16; i++) { f[i] = __expf(f[i] - m); sum += f[i]; }
    #pragma unroll
    for (int o = 16; o > 0; o >>= 1)
        sum += __shfl_xor_sync(0xFFFFFFFF, sum, o);
    __syncthreads();
    if (lane == 0) red[wp] = sum;
    __syncthreads();
    {
        float t = red[lane & 7];
        #pragma unroll
        for (int o = 4; o > 0; o >>= 1)
            t += __shfl_xor_sync(0xFFFFFFFF, t, o);
        sum = t;
    }
    const float inv = 1.0f / sum;

    __half2 h[8];
    #pragma unroll
    for (int i = 0; i < 8; i++)
        h[i] = __floats2half2_rn(f[i * 2] * inv, f[i * 2 + 1] * inv);
    uint4 o[2];
    {
        uint32_t* w = reinterpret_cast<uint32_t*>(o);
        #pragma unroll
        for (int i = 0; i < 8; i++) w[i] = *(uint32_t*)&h[i];
    }
    p[tid * 2]     = o[0];
    p[tid * 2 + 1] = o[1];
}

// ---------------------------------------------------------------------------
extern "C" void kernel_launch(void* const* d_in, const int* in_sizes, int n_in,
                              void* d_out, int out_size)
{
    const float* x  = (const float*)d_in[0];
    const float* Wq = (const float*)d_in[1];
    const float* bq = (const float*)d_in[2];
    const float* Wk = (const float*)d_in[3];
    const float* bk = (const float*)d_in[4];
    const float* Wv = (const float*)d_in[5];
    const float* bv = (const float*)d_in[6];
    const float* Wp = (const float*)d_in[7];
    const float* bp = (const float*)d_in[8];
    float* out = (float*)d_out;

    __half *xh, *QKV, *VT, *S, *C, *WQKVT, *WPT;
    float* bqkv;
    cudaGetSymbolAddress((void**)&xh,    g_xh);
    cudaGetSymbolAddress((void**)&QKV,   g_QKV);
    cudaGetSymbolAddress((void**)&VT,    g_VT);
    cudaGetSymbolAddress((void**)&S,     g_S);
    cudaGetSymbolAddress((void**)&C,     g_C);
    cudaGetSymbolAddress((void**)&WQKVT, g_WQKVT);
    cudaGetSymbolAddress((void**)&WPT,   g_WPT);
    cudaGetSymbolAddress((void**)&bqkv,  g_bqkv);

    cudaFuncSetAttribute(gemm_f16<true>,  cudaFuncAttributeMaxDynamicSharedMemorySize, SM_TOTAL);
    cudaFuncSetAttribute(gemm_f16<false>, cudaFuncAttributeMaxDynamicSharedMemorySize, SM_TOTAL);

    const float scale = 1.0f / sqrtf((float)U_);

    // 0) setup: x->fp16, transpose weights, pack bias
    conv_f16<<<(M1 * U_ / 4 + 255) / 256, 256>>>(x, xh, (long long)M1 * U_);
    {
        dim3 tb(32, 8, 1), g(U_ / 32, U_ / 32, 4);
        wtrans_all<<<g, tb>>>(Wq, Wk, Wv, Wp, WQKVT, WPT);
    }
    pack_bias<<<6, 256>>>(bq, bk, bv, bqkv);

    // 1) QKV projection: [16384,1536] = xh @ Wqkv^T + bqkv -> fp16 interleaved
    {
        dim3 g(QKVLD / BN, M1 / BM, 1);
        gemm_f16<true><<<g, 256, SM_TOTAL>>>(xh, WQKVT, bqkv, nullptr, QKV,
                                             QKVLD, U_, U_, U_, QKVLD,
                                             0, 0, 0, 1.0f);
    }

    // 2) V^T per batch [512, 4096]
    {
        dim3 tb(32, 8, 1), g(U_ / 32, N_ / 32, B_);
        vtrans<<<g, tb>>>(QKV, VT);
    }

    // 3) S[b] = scale * Q[b] @ K[b]^T -> fp16
    {
        dim3 g(N_ / BN, N_ / BM, B_);
        gemm_f16<true><<<g, 256, SM_TOTAL>>>(QKV, QKV + U_, nullptr, nullptr, S,
                                             N_, U_, QKVLD, QKVLD, N_,
                                             (long long)N_ * QKVLD, (long long)N_ * QKVLD,
                                             (long long)N_ * N_, scale);
    }

    // 4) softmax rows in place
    softmax_f16<<<B_ * N_, 256>>>(S);

    // 5) ctx[b] = P[b] @ V[b]   (B operand = V^T rows)
    {
        dim3 g(U_ / BN, N_ / BM, B_);
        gemm_f16<true><<<g, 256, SM_TOTAL>>>(S, VT, nullptr, nullptr, C,
                                             U_, N_, N_, N_, U_,
                                             (long long)N_ * N_, (long long)U_ * N_,
                                             (long long)N_ * U_, 1.0f);
    }

    // 6) out = x + ctx @ Wp^T + bp  (fp32 out, residual)
    {
        dim3 g(U_ / BN, M1 / BM, 1);
        gemm_f16<false><<<g, 256, SM_TOTAL>>>(C, WPT, bp, x, out,
                                              U_, U_, U_, U_, U_,
                                              0, 0, 0, 1.0f);
    }
}

// round 17
// speedup vs baseline: 1.0150x; 1.0150x over previous
#include <cuda_runtime.h>
#include <cuda_fp16.h>
#include <math.h>
#include <stdint.h>

// Problem constants
#define B_  4
#define N_  4096
#define U_  512
#define M1  (B_ * N_)
#define QKVLD 1536

// GEMM tiling: CTA 128x128, 8 warps 64x32, BK=64, 3-stage cp.async pipeline
#define BM 128
#define BN 128
#define SKB 144          // smem row stride bytes (128 data + 16 pad)
#define NSTAGE 3

static constexpr int ATILE  = BM * SKB;            // 18432 B
static constexpr int STAGEB = 2 * ATILE;
static constexpr int SM_TOTAL = NSTAGE * STAGEB;   // 110592 B

// ---------------- scratch (device globals; no allocation allowed) ----------
__device__ __align__(16) __half g_xh  [(size_t)M1 * U_];
__device__ __align__(16) __half g_QKV [(size_t)M1 * QKVLD];    // Q|K|V per row
__device__ __align__(16) __half g_VT  [(size_t)M1 * U_];       // per batch [U, N]
__device__ __align__(16) __half g_S   [(size_t)B_ * N_ * N_];  // 128 MB scores/probs
__device__ __align__(16) __half g_C   [(size_t)M1 * U_];       // ctx
__device__ __align__(16) __half g_WQKVT[(size_t)3 * U_ * U_];  // [1536,512]
__device__ __align__(16) __half g_WPT [(size_t)U_ * U_];
__device__ __align__(16) float  g_bqkv[QKVLD];

// ---------------- PTX helpers ----------------------------------------------
__device__ __forceinline__ uint32_t smem_u32(const void* p) {
    uint32_t a;
    asm("{ .reg .u64 t; cvta.to.shared.u64 t, %1; cvt.u32.u64 %0, t; }" : "=r"(a) : "l"(p));
    return a;
}
#define CP_ASYNC16(dst, src) \
    asm volatile("cp.async.cg.shared.global [%0], [%1], 16;\n" :: "r"(dst), "l"(src))
#define CP_COMMIT() asm volatile("cp.async.commit_group;\n" ::: "memory")
#define CP_WAIT(n)  asm volatile("cp.async.wait_group %0;\n" :: "n"(n) : "memory")

__device__ __forceinline__ void ldsm_x4(uint32_t& r0, uint32_t& r1, uint32_t& r2,
                                        uint32_t& r3, uint32_t addr) {
    asm volatile("ldmatrix.sync.aligned.m8n8.x4.shared.b16 {%0,%1,%2,%3}, [%4];"
                 : "=r"(r0), "=r"(r1), "=r"(r2), "=r"(r3) : "r"(addr));
}
// f16 x f16 -> f16 accumulate; c = two packed f16x2 regs
__device__ __forceinline__ void mma_f16(uint32_t c[2],
                                        uint32_t a0, uint32_t a1, uint32_t a2, uint32_t a3,
                                        uint32_t b0, uint32_t b1) {
    asm volatile(
        "mma.sync.aligned.m16n8k16.row.col.f16.f16.f16.f16 "
        "{%0,%1}, {%2,%3,%4,%5}, {%6,%7}, {%0,%1};\n"
        : "+r"(c[0]), "+r"(c[1])
        : "r"(a0), "r"(a1), "r"(a2), "r"(a3), "r"(b0), "r"(b1));
}

// ---------------------------------------------------------------------------
// fp16 NT GEMM (f16 accum) with explicit fragment double-buffering.
// A: [M,K] lda-strided __half. B: [N,K] ldb-strided __half.
// 256 threads, 8 warps 64x32. 3-stage cp.async pipeline, 1 barrier/ktile.
// ---------------------------------------------------------------------------
template <bool OF16>
__global__ __launch_bounds__(256, 2)
void gemm_f16(const __half* __restrict__ A,
              const __half* __restrict__ Bm,
              const float* __restrict__ bias,
              const float* __restrict__ residual,
              void* __restrict__ Cout,
              int N, int K, int lda, int ldb, int ldc,
              long long sA, long long sB, long long sC,
              float scale)
{
    extern __shared__ char smem[];
    const uint32_t sbase = smem_u32(smem);
    const int tid  = threadIdx.x;
    const int wid  = tid >> 5;
    const int lane = tid & 31;

    const int z = blockIdx.z;
    A  += (long long)z * sA;
    Bm += (long long)z * sB;

    const int rowBase = blockIdx.y * BM;
    const int colBase = blockIdx.x * BN;
    const int warpM = (wid & 1) * 64;
    const int warpN = (wid >> 1) * 32;

    const __half* Aptr = A + (long long)rowBase * lda;
    const __half* Bptr = Bm + (long long)colBase * ldb;

    uint32_t acc[4][4][2];
    #pragma unroll
    for (int mi = 0; mi < 4; mi++)
        #pragma unroll
        for (int ni = 0; ni < 4; ni++) {
            acc[mi][ni][0] = 0u; acc[mi][ni][1] = 0u;
        }

    const int lr = tid >> 3;
    const int lc = tid & 7;
    auto load_tile = [&](int s, int k0) {
        const uint32_t abase = sbase + s * STAGEB;
        const uint32_t bbase = abase + ATILE;
        #pragma unroll
        for (int i = 0; i < 4; i++) {
            const int r = lr + i * 32;
            CP_ASYNC16(abase + r * SKB + lc * 16,
                       Aptr + (long long)r * lda + k0 + lc * 8);
        }
        #pragma unroll
        for (int i = 0; i < 4; i++) {
            const int r = lr + i * 32;
            CP_ASYNC16(bbase + r * SKB + lc * 16,
                       Bptr + (long long)r * ldb + k0 + lc * 8);
        }
        CP_COMMIT();
    };

    const int lm = lane & 7;
    const int lt = lane >> 3;
    const int aRowOff = lm + (lt & 1) * 8;
    const int aKOff   = (lt >> 1) * 8;
    const int bRowOff = lm + (lt >> 1) * 8;
    const int bKOff   = (lt & 1) * 8;

    // fragment double buffers
    uint32_t a[2][4][4], b[2][4][2];
    auto load_frags = [&](int buf, uint32_t Asb, uint32_t Bsb, int kk) {
        #pragma unroll
        for (int mi = 0; mi < 4; mi++) {
            uint32_t addr = Asb + (warpM + mi * 16 + aRowOff) * SKB
                          + (kk * 16 + aKOff) * 2;
            ldsm_x4(a[buf][mi][0], a[buf][mi][1], a[buf][mi][2], a[buf][mi][3], addr);
        }
        #pragma unroll
        for (int p = 0; p < 2; p++) {
            uint32_t addr = Bsb + (warpN + p * 16 + bRowOff) * SKB
                          + (kk * 16 + bKOff) * 2;
            uint32_t r0, r1, r2, r3;
            ldsm_x4(r0, r1, r2, r3, addr);
            b[buf][2*p][0] = r0;   b[buf][2*p][1] = r1;
            b[buf][2*p+1][0] = r2; b[buf][2*p+1][1] = r3;
        }
    };

    const int T = K / 64;
    load_tile(0, 0);
    if (T > 1) load_tile(1, 64);

    int sIdx = 0;
    for (int t = 0; t < T; t++) {
        if (t + 1 < T) { CP_WAIT(1); } else { CP_WAIT(0); }
        __syncthreads();

        const uint32_t Asb = sbase + sIdx * STAGEB;
        const uint32_t Bsb = Asb + ATILE;

        // start fragment pipeline for this tile immediately
        load_frags(0, Asb, Bsb, 0);

        // then issue gmem prefetch for t+2
        if (t + 2 < T) {
            int s2 = sIdx + 2; if (s2 >= NSTAGE) s2 -= NSTAGE;
            load_tile(s2, (t + 2) * 64);
        }

        #pragma unroll
        for (int kk = 0; kk < 4; kk++) {
            const int cur = kk & 1;
            if (kk < 3) load_frags(cur ^ 1, Asb, Bsb, kk + 1);
            #pragma unroll
            for (int mi = 0; mi < 4; mi++)
                #pragma unroll
                for (int ni = 0; ni < 4; ni++)
                    mma_f16(acc[mi][ni],
                            a[cur][mi][0], a[cur][mi][1], a[cur][mi][2], a[cur][mi][3],
                            b[cur][ni][0], b[cur][ni][1]);
        }
        sIdx++; if (sIdx >= NSTAGE) sIdx = 0;
    }

    // ---- epilogue ----
    #pragma unroll
    for (int mi = 0; mi < 4; mi++) {
        #pragma unroll
        for (int ni = 0; ni < 4; ni++) {
            const int row0 = rowBase + warpM + mi * 16 + (lane >> 2);
            const int col  = colBase + warpN + ni * 8 + (lane & 3) * 2;
            float2 v01 = __half22float2(*reinterpret_cast<__half2*>(&acc[mi][ni][0]));
            float2 v23 = __half22float2(*reinterpret_cast<__half2*>(&acc[mi][ni][1]));
            float v[4] = { v01.x * scale, v01.y * scale, v23.x * scale, v23.y * scale };
            if (bias) {
                const float b0 = bias[col], b1 = bias[col + 1];
                v[0] += b0; v[1] += b1; v[2] += b0; v[3] += b1;
            }
            if (!OF16) {
                float* C = (float*)Cout + (long long)z * sC;
                if (residual) {
                    const float* R = residual + (long long)z * sC;
                    float2 r0 = *reinterpret_cast<const float2*>(&R[(long long)row0 * ldc + col]);
                    float2 r1 = *reinterpret_cast<const float2*>(&R[(long long)(row0 + 8) * ldc + col]);
                    v[0] += r0.x; v[1] += r0.y; v[2] += r1.x; v[3] += r1.y;
                }
                *reinterpret_cast<float2*>(&C[(long long)row0 * ldc + col])       = make_float2(v[0], v[1]);
                *reinterpret_cast<float2*>(&C[(long long)(row0 + 8) * ldc + col]) = make_float2(v[2], v[3]);
            } else {
                __half* C = (__half*)Cout + (long long)z * sC;
                __half2 p0 = __floats2half2_rn(v[0], v[1]);
                __half2 p1 = __floats2half2_rn(v[2], v[3]);
                *reinterpret_cast<uint32_t*>(&C[(long long)row0 * ldc + col])       = *(uint32_t*)&p0;
                *reinterpret_cast<uint32_t*>(&C[(long long)(row0 + 8) * ldc + col]) = *(uint32_t*)&p1;
            }
        }
    }
}

// ---------------------------------------------------------------------------
// setup: fp32 -> fp16 x, pack biases, weight transposes
// ---------------------------------------------------------------------------
__global__ __launch_bounds__(256)
void conv_f16(const float* __restrict__ in, __half* __restrict__ out, long long n)
{
    long long i = ((long long)blockIdx.x * blockDim.x + threadIdx.x) * 4;
    if (i >= n) return;
    float4 f = *reinterpret_cast<const float4*>(in + i);
    __half2 p0 = __floats2half2_rn(f.x, f.y);
    __half2 p1 = __floats2half2_rn(f.z, f.w);
    uint2 o; o.x = *(uint32_t*)&p0; o.y = *(uint32_t*)&p1;
    *reinterpret_cast<uint2*>(out + i) = o;
}

__global__ __launch_bounds__(256)
void pack_bias(const float* __restrict__ bq, const float* __restrict__ bk,
               const float* __restrict__ bv, float* __restrict__ bqkv)
{
    int i = blockIdx.x * blockDim.x + threadIdx.x;
    if (i < U_)              bqkv[i] = bq[i];
    else if (i < 2 * U_)     bqkv[i] = bk[i - U_];
    else if (i < 3 * U_)     bqkv[i] = bv[i - 2 * U_];
}

// all-weights transpose fp32->fp16: z in {0:Wq,1:Wk,2:Wv,3:Wp}
__global__ __launch_bounds__(256)
void wtrans_all(const float* __restrict__ Wq, const float* __restrict__ Wk,
                const float* __restrict__ Wv, const float* __restrict__ Wp,
                __half* __restrict__ Wqkvt, __half* __restrict__ Wpt)
{
    __shared__ float tile[32][33];
    const int z = blockIdx.z;
    const float* in = (z == 0) ? Wq : (z == 1) ? Wk : (z == 2) ? Wv : Wp;
    __half* out = (z < 3) ? (Wqkvt + (size_t)z * U_ * U_) : Wpt;
    const int c0 = blockIdx.x * 32, r0 = blockIdx.y * 32;
    const int x = threadIdx.x, y = threadIdx.y;
    #pragma unroll
    for (int i = 0; i < 32; i += 8)
        tile[y + i][x] = in[(long long)(r0 + y + i) * U_ + c0 + x];
    __syncthreads();
    #pragma unroll
    for (int i = 0; i < 32; i += 8)
        out[(long long)(c0 + y + i) * U_ + r0 + x] = __float2half(tile[x][y + i]);
}

// V (inside QKV, row stride 1536, col offset 1024) -> VT [U, N] per batch
__global__ __launch_bounds__(256)
void vtrans(const __half* __restrict__ qkv, __half* __restrict__ vt)
{
    __shared__ __half tile[32][34];
    const int z = blockIdx.z;
    const __half* in = qkv + (long long)z * N_ * QKVLD + 2 * U_;
    __half* out = vt + (long long)z * N_ * U_;
    const int c0 = blockIdx.x * 32, r0 = blockIdx.y * 32;
    const int x = threadIdx.x, y = threadIdx.y;
    #pragma unroll
    for (int i = 0; i < 32; i += 8)
        tile[y + i][x] = in[(long long)(r0 + y + i) * QKVLD + c0 + x];
    __syncthreads();
    #pragma unroll
    for (int i = 0; i < 32; i += 8)
        out[(long long)(c0 + y + i) * N_ + r0 + x] = tile[x][y + i];
}

// ---------------------------------------------------------------------------
// row softmax on fp16 [rows x 4096], in place; warp-shuffle reductions
// ---------------------------------------------------------------------------
__global__ __launch_bounds__(256)
void softmax_f16(__half* __restrict__ S)
{
    const long long row = blockIdx.x;
    uint4* p = reinterpret_cast<uint4*>(S + row * (long long)N_);
    const int tid = threadIdx.x;
    const int lane = tid & 31, wp = tid >> 5;
    __shared__ float red[8];

    uint4 u[2];
    u[0] = p[tid * 2];
    u[1] = p[tid * 2 + 1];

    float f[16];
    {
        const __half2* h = reinterpret_cast<const __half2*>(u);
        #pragma unroll
        for (int i = 0; i < 8; i++) {
            float2 t = __half22float2(h[i]);
            f[i * 2] = t.x; f[i * 2 + 1] = t.y;
        }
    }

    float m = f[0];
    #pragma unroll
    for (int i = 1; i < 16; i++) m = fmaxf(m, f[i]);
    #pragma unroll
    for (int o = 16; o > 0; o >>= 1)
        m = fmaxf(m, __shfl_xor_sync(0xFFFFFFFF, m, o));
    if (lane == 0) red[wp] = m;
    __syncthreads();
    {
        float t = red[lane & 7];
        #pragma unroll
        for (int o = 4; o > 0; o >>= 1)
            t = fmaxf(t, __shfl_xor_sync(0xFFFFFFFF, t, o));
        m = t;
    }

    float sum = 0.0f;
    #pragma unroll
    for (int i = 0; i < 16; i++) { f[i] = __expf(f[i] - m); sum += f[i]; }
    #pragma unroll
    for (int o = 16; o > 0; o >>= 1)
        sum += __shfl_xor_sync(0xFFFFFFFF, sum, o);
    __syncthreads();
    if (lane == 0) red[wp] = sum;
    __syncthreads();
    {
        float t = red[lane & 7];
        #pragma unroll
        for (int o = 4; o > 0; o >>= 1)
            t += __shfl_xor_sync(0xFFFFFFFF, t, o);
        sum = t;
    }
    const float inv = 1.0f / sum;

    __half2 h[8];
    #pragma unroll
    for (int i = 0; i < 8; i++)
        h[i] = __floats2half2_rn(f[i * 2] * inv, f[i * 2 + 1] * inv);
    uint4 o[2];
    {
        uint32_t* w = reinterpret_cast<uint32_t*>(o);
        #pragma unroll
        for (int i = 0; i < 8; i++) w[i] = *(uint32_t*)&h[i];
    }
    p[tid * 2]     = o[0];
    p[tid * 2 + 1] = o[1];
}

// ---------------------------------------------------------------------------
extern "C" void kernel_launch(void* const* d_in, const int* in_sizes, int n_in,
                              void* d_out, int out_size)
{
    const float* x  = (const float*)d_in[0];
    const float* Wq = (const float*)d_in[1];
    const float* bq = (const float*)d_in[2];
    const float* Wk = (const float*)d_in[3];
    const float* bk = (const float*)d_in[4];
    const float* Wv = (const float*)d_in[5];
    const float* bv = (const float*)d_in[6];
    const float* Wp = (const float*)d_in[7];
    const float* bp = (const float*)d_in[8];
    float* out = (float*)d_out;

    __half *xh, *QKV, *VT, *S, *C, *WQKVT, *WPT;
    float* bqkv;
    cudaGetSymbolAddress((void**)&xh,    g_xh);
    cudaGetSymbolAddress((void**)&QKV,   g_QKV);
    cudaGetSymbolAddress((void**)&VT,    g_VT);
    cudaGetSymbolAddress((void**)&S,     g_S);
    cudaGetSymbolAddress((void**)&C,     g_C);
    cudaGetSymbolAddress((void**)&WQKVT, g_WQKVT);
    cudaGetSymbolAddress((void**)&WPT,   g_WPT);
    cudaGetSymbolAddress((void**)&bqkv,  g_bqkv);

    cudaFuncSetAttribute(gemm_f16<true>,  cudaFuncAttributeMaxDynamicSharedMemorySize, SM_TOTAL);
    cudaFuncSetAttribute(gemm_f16<false>, cudaFuncAttributeMaxDynamicSharedMemorySize, SM_TOTAL);

    const float scale = 1.0f / sqrtf((float)U_);

    // 0) setup: x->fp16, transpose weights, pack bias
    conv_f16<<<(M1 * U_ / 4 + 255) / 256, 256>>>(x, xh, (long long)M1 * U_);
    {
        dim3 tb(32, 8, 1), g(U_ / 32, U_ / 32, 4);
        wtrans_all<<<g, tb>>>(Wq, Wk, Wv, Wp, WQKVT, WPT);
    }
    pack_bias<<<6, 256>>>(bq, bk, bv, bqkv);

    // 1) QKV projection: [16384,1536] = xh @ Wqkv^T + bqkv -> fp16 interleaved
    {
        dim3 g(QKVLD / BN, M1 / BM, 1);
        gemm_f16<true><<<g, 256, SM_TOTAL>>>(xh, WQKVT, bqkv, nullptr, QKV,
                                             QKVLD, U_, U_, U_, QKVLD,
                                             0, 0, 0, 1.0f);
    }

    // 2) V^T per batch [512, 4096]
    {
        dim3 tb(32, 8, 1), g(U_ / 32, N_ / 32, B_);
        vtrans<<<g, tb>>>(QKV, VT);
    }

    // 3) S[b] = scale * Q[b] @ K[b]^T -> fp16
    {
        dim3 g(N_ / BN, N_ / BM, B_);
        gemm_f16<true><<<g, 256, SM_TOTAL>>>(QKV, QKV + U_, nullptr, nullptr, S,
                                             N_, U_, QKVLD, QKVLD, N_,
                                             (long long)N_ * QKVLD, (long long)N_ * QKVLD,
                                             (long long)N_ * N_, scale);
    }

    // 4) softmax rows in place
    softmax_f16<<<B_ * N_, 256>>>(S);

    // 5) ctx[b] = P[b] @ V[b]   (B operand = V^T rows)
    {
        dim3 g(U_ / BN, N_ / BM, B_);
        gemm_f16<true><<<g, 256, SM_TOTAL>>>(S, VT, nullptr, nullptr, C,
                                             U_, N_, N_, N_, U_,
                                             (long long)N_ * N_, (long long)U_ * N_,
                                             (long long)N_ * U_, 1.0f);
    }

    // 6) out = x + ctx @ Wp^T + bp  (fp32 out, residual)
    {
        dim3 g(U_ / BN, M1 / BM, 1);
        gemm_f16<false><<<g, 256, SM_TOTAL>>>(C, WPT, bp, x, out,
                                              U_, U_, U_, U_, U_,
                                              0, 0, 0, 1.0f);
    }
}